// round 2
// baseline (speedup 1.0000x reference)
#include <cuda_runtime.h>

#define N_NODES 40000
#define N_EDGES 640000
#define D_IN    512
#define D_OUT   128

// 20.5 MB scratch for seq = x @ W^T  (allocation-free rule: __device__ global)
__device__ __align__(16) float g_seq[(size_t)N_NODES * D_OUT];

// ---------------------------------------------------------------------------
// GEMM: seq[n][o] = sum_k x[n][k] * w[o][k]
// 128x128 block tile, BK=16, 256 threads, 8x8 per-thread microtile.
// ---------------------------------------------------------------------------
__global__ __launch_bounds__(256) void gcn_gemm_kernel(
    const float* __restrict__ x, const float* __restrict__ w)
{
    __shared__ float As[128][16];   // [m][k]
    __shared__ float Bs[16][128];   // [k][o]

    const int m0  = blockIdx.x * 128;
    const int tid = threadIdx.x;
    const int tx  = tid & 15;   // output-col group (8 cols each)
    const int ty  = tid >> 4;   // output-row group (8 rows each)

    float acc[8][8];
#pragma unroll
    for (int i = 0; i < 8; i++)
#pragma unroll
        for (int j = 0; j < 8; j++) acc[i][j] = 0.f;

    for (int k0 = 0; k0 < D_IN; k0 += 16) {
        // cooperative loads: 2048 elements each of A-tile and B-tile, 8/thread
#pragma unroll
        for (int i = 0; i < 8; i++) {
            int e  = tid + i * 256;
            int kk = e & 15;
            int r  = e >> 4;                    // 0..127
            int gm = m0 + r;
            As[r][kk] = (gm < N_NODES) ? x[(size_t)gm * D_IN + k0 + kk] : 0.f;
            Bs[kk][r] = w[(size_t)r * D_IN + k0 + kk];   // r = output channel o
        }
        __syncthreads();

#pragma unroll
        for (int kk = 0; kk < 16; kk++) {
            float a[8];
#pragma unroll
            for (int i = 0; i < 8; i++) a[i] = As[ty * 8 + i][kk];
            float4 b0 = *reinterpret_cast<const float4*>(&Bs[kk][tx * 8]);
            float4 b1 = *reinterpret_cast<const float4*>(&Bs[kk][tx * 8 + 4]);
            float b[8] = {b0.x, b0.y, b0.z, b0.w, b1.x, b1.y, b1.z, b1.w};
#pragma unroll
            for (int i = 0; i < 8; i++)
#pragma unroll
                for (int j = 0; j < 8; j++)
                    acc[i][j] = fmaf(a[i], b[j], acc[i][j]);
        }
        __syncthreads();
    }

    // store 8x8 microtile (two float4 per row)
#pragma unroll
    for (int i = 0; i < 8; i++) {
        int gm = m0 + ty * 8 + i;
        if (gm < N_NODES) {
            float* dst = &g_seq[(size_t)gm * D_OUT + tx * 8];
            *reinterpret_cast<float4*>(dst) =
                make_float4(acc[i][0], acc[i][1], acc[i][2], acc[i][3]);
            *reinterpret_cast<float4*>(dst + 4) =
                make_float4(acc[i][4], acc[i][5], acc[i][6], acc[i][7]);
        }
    }
}

// ---------------------------------------------------------------------------
// init: out[n][c] = bias[c]  (vectorized float4; bias has 128 floats = 32 f4)
// ---------------------------------------------------------------------------
__global__ __launch_bounds__(256) void gcn_init_kernel(
    float4* __restrict__ out4, const float4* __restrict__ bias4)
{
    int i = blockIdx.x * blockDim.x + threadIdx.x;   // over 40000*32 float4
    if (i < N_NODES * (D_OUT / 4)) {
        out4[i] = bias4[i & 31];
    }
}

// ---------------------------------------------------------------------------
// scatter: one warp per edge.
// out[row] += val * seq[col]   via red.global.add.v4.f32 (1 RED.128 per lane)
// ---------------------------------------------------------------------------
__global__ __launch_bounds__(256) void gcn_scatter_kernel(
    const float* __restrict__ edge_val,
    const int*   __restrict__ edge_row,
    const int*   __restrict__ edge_col,
    float*       __restrict__ out)
{
    int e = (int)((blockIdx.x * blockDim.x + threadIdx.x) >> 5);
    if (e >= N_EDGES) return;
    int lane = threadIdx.x & 31;

    int   row = __ldg(edge_row + e);
    int   col = __ldg(edge_col + e);
    float v   = __ldg(edge_val + e);

    const float4 s = *(reinterpret_cast<const float4*>(g_seq) +
                       (size_t)col * (D_OUT / 4) + lane);
    float4* dst = reinterpret_cast<float4*>(out) + (size_t)row * (D_OUT / 4) + lane;

    asm volatile(
        "red.global.add.v4.f32 [%0], {%1, %2, %3, %4};"
        :: "l"(dst), "f"(s.x * v), "f"(s.y * v), "f"(s.z * v), "f"(s.w * v)
        : "memory");
}

// ---------------------------------------------------------------------------
// PReLU epilogue: out = out > 0 ? out : alpha * out   (single shared alpha)
// ---------------------------------------------------------------------------
__global__ __launch_bounds__(256) void gcn_prelu_kernel(
    float4* __restrict__ out4, const float* __restrict__ alpha)
{
    int i = blockIdx.x * blockDim.x + threadIdx.x;
    if (i < N_NODES * (D_OUT / 4)) {
        float a  = __ldg(alpha);
        float4 v = out4[i];
        v.x = v.x > 0.f ? v.x : a * v.x;
        v.y = v.y > 0.f ? v.y : a * v.y;
        v.z = v.z > 0.f ? v.z : a * v.z;
        v.w = v.w > 0.f ? v.w : a * v.w;
        out4[i] = v;
    }
}

// ---------------------------------------------------------------------------
// Inputs (metadata order): x, weight, bias, alpha, edge_val, edge_row, edge_col
// Output: float32 [40000, 128]
// ---------------------------------------------------------------------------
extern "C" void kernel_launch(void* const* d_in, const int* in_sizes, int n_in,
                              void* d_out, int out_size)
{
    const float* x        = (const float*)d_in[0];
    const float* weight   = (const float*)d_in[1];
    const float* bias     = (const float*)d_in[2];
    const float* alpha    = (const float*)d_in[3];
    const float* edge_val = (const float*)d_in[4];
    const int*   edge_row = (const int*)  d_in[5];
    const int*   edge_col = (const int*)  d_in[6];
    float*       out      = (float*)d_out;

    (void)in_sizes; (void)n_in; (void)out_size;

    // 1) seq = x @ W^T
    gcn_gemm_kernel<<<(N_NODES + 127) / 128, 256>>>(x, weight);

    // 2) out = bias (broadcast)
    const int n4 = N_NODES * (D_OUT / 4);           // 1,280,000 float4
    gcn_init_kernel<<<(n4 + 255) / 256, 256>>>(
        (float4*)out, (const float4*)bias);

    // 3) out[row] += val * seq[col] for every edge (vector RED atomics)
    const long long threads = (long long)N_EDGES * 32;
    gcn_scatter_kernel<<<(unsigned)((threads + 255) / 256), 256>>>(
        edge_val, edge_row, edge_col, out);

    // 4) PReLU
    gcn_prelu_kernel<<<(n4 + 255) / 256, 256>>>((float4*)out, alpha);
}

// round 4
// speedup vs baseline: 2.3381x; 2.3381x over previous
#include <cuda_runtime.h>
#include <cstdint>

#define N_NODES 40000
#define N_EDGES 640000
#define D_IN    512
#define D_OUT   128

// 20.5 MB scratch for seq = x @ W^T  (allocation-free rule: __device__ global)
__device__ __align__(16) float g_seq[(size_t)N_NODES * D_OUT];

// ---------------------------------------------------------------------------
// tf32 helpers
// ---------------------------------------------------------------------------
__device__ __forceinline__ uint32_t f2tf32(float f) {
    uint32_t u;
    asm("cvt.rna.tf32.f32 %0, %1;" : "=r"(u) : "f"(f));
    return u;
}

__device__ __forceinline__ void mma_tf32(float* c, const uint32_t* a,
                                         uint32_t b0, uint32_t b1) {
    asm volatile(
        "mma.sync.aligned.m16n8k8.row.col.f32.tf32.tf32.f32 "
        "{%0,%1,%2,%3}, {%4,%5,%6,%7}, {%8,%9}, {%0,%1,%2,%3};"
        : "+f"(c[0]), "+f"(c[1]), "+f"(c[2]), "+f"(c[3])
        : "r"(a[0]), "r"(a[1]), "r"(a[2]), "r"(a[3]), "r"(b0), "r"(b1));
}

// ---------------------------------------------------------------------------
// GEMM: seq[n][o] = sum_k x[n][k] * w[o][k]   (tf32 tensor cores)
// Block tile 128(M) x 128(N) x BK=32. 256 threads = 8 warps (4x2),
// warp tile 32x64, m16n8k8 fragments. Smem rows padded to 36 floats
// (conflict-free fragment gathers + 16B-aligned STS.128).
// ---------------------------------------------------------------------------
#define BK 32
#define LDS_PAD 36   // 36*4 = 144 bytes per row, 144 % 16 == 0

__global__ __launch_bounds__(256, 1) void gcn_gemm_tf32_kernel(
    const float* __restrict__ x, const float* __restrict__ w)
{
    __shared__ uint32_t As[128 * LDS_PAD];   // [m][k] tf32
    __shared__ uint32_t Bs[128 * LDS_PAD];   // [n][k] tf32

    const int tid    = threadIdx.x;
    const int lane   = tid & 31;
    const int wid    = tid >> 5;
    const int warp_m = wid & 3;    // 0..3 -> 32-row slice
    const int warp_n = wid >> 2;   // 0..1 -> 64-col slice
    const int m0     = blockIdx.x * 128;

    // loader mapping: each thread owns quad q of row mrow (+r*32)
    const int q    = tid & 7;      // 0..7  -> cols q*4..q*4+3 within BK=32
    const int mrow = tid >> 3;     // 0..31

    float acc[2][8][4];
#pragma unroll
    for (int mt = 0; mt < 2; mt++)
#pragma unroll
        for (int nt = 0; nt < 8; nt++)
#pragma unroll
            for (int j = 0; j < 4; j++) acc[mt][nt][j] = 0.f;

    float4 xv[4], wv[4];

    // prologue load (k0 = 0)
#pragma unroll
    for (int r = 0; r < 4; r++) {
        int m  = mrow + r * 32;
        int gm = m0 + m;
        xv[r] = (gm < N_NODES)
            ? *reinterpret_cast<const float4*>(x + (size_t)gm * D_IN + q * 4)
            : make_float4(0.f, 0.f, 0.f, 0.f);
        wv[r] = *reinterpret_cast<const float4*>(w + (size_t)m * D_IN + q * 4);
    }

#pragma unroll 1
    for (int kt = 0; kt < D_IN / BK; kt++) {
        // stage current regs -> smem (converted to tf32), STS.128
#pragma unroll
        for (int r = 0; r < 4; r++) {
            int m    = mrow + r * 32;
            int base = m * LDS_PAD + q * 4;
            uint4 ta = make_uint4(f2tf32(xv[r].x), f2tf32(xv[r].y),
                                  f2tf32(xv[r].z), f2tf32(xv[r].w));
            uint4 tb = make_uint4(f2tf32(wv[r].x), f2tf32(wv[r].y),
                                  f2tf32(wv[r].z), f2tf32(wv[r].w));
            *reinterpret_cast<uint4*>(&As[base]) = ta;
            *reinterpret_cast<uint4*>(&Bs[base]) = tb;
        }
        __syncthreads();

        // prefetch next tile while computing this one
        const bool more = (kt + 1) < (D_IN / BK);
        float4 xn[4], wn[4];
        if (more) {
            int k0 = (kt + 1) * BK;
#pragma unroll
            for (int r = 0; r < 4; r++) {
                int m  = mrow + r * 32;
                int gm = m0 + m;
                xn[r] = (gm < N_NODES)
                    ? *reinterpret_cast<const float4*>(
                          x + (size_t)gm * D_IN + k0 + q * 4)
                    : make_float4(0.f, 0.f, 0.f, 0.f);
                wn[r] = *reinterpret_cast<const float4*>(
                    w + (size_t)m * D_IN + k0 + q * 4);
            }
        }

        // 4 k8 steps
#pragma unroll
        for (int ks = 0; ks < 4; ks++) {
            const int kk = ks * 8;
            uint32_t a[2][4];
#pragma unroll
            for (int mt = 0; mt < 2; mt++) {
                int mr = warp_m * 32 + mt * 16 + (lane >> 2);
                int kc = kk + (lane & 3);
                a[mt][0] = As[mr * LDS_PAD + kc];
                a[mt][1] = As[(mr + 8) * LDS_PAD + kc];
                a[mt][2] = As[mr * LDS_PAD + kc + 4];
                a[mt][3] = As[(mr + 8) * LDS_PAD + kc + 4];
            }
#pragma unroll
            for (int nt = 0; nt < 8; nt++) {
                int nr = warp_n * 64 + nt * 8 + (lane >> 2);
                uint32_t b0 = Bs[nr * LDS_PAD + kk + (lane & 3)];
                uint32_t b1 = Bs[nr * LDS_PAD + kk + (lane & 3) + 4];
                mma_tf32(acc[0][nt], a[0], b0, b1);
                mma_tf32(acc[1][nt], a[1], b0, b1);
            }
        }
        __syncthreads();

        if (more) {
#pragma unroll
            for (int r = 0; r < 4; r++) { xv[r] = xn[r]; wv[r] = wn[r]; }
        }
    }

    // epilogue: write 32x64 warp tile to g_seq
#pragma unroll
    for (int mt = 0; mt < 2; mt++) {
        int r0 = m0 + warp_m * 32 + mt * 16 + (lane >> 2);
        int r1 = r0 + 8;
#pragma unroll
        for (int nt = 0; nt < 8; nt++) {
            int c0 = warp_n * 64 + nt * 8 + (lane & 3) * 2;
            if (r0 < N_NODES)
                *reinterpret_cast<float2*>(&g_seq[(size_t)r0 * D_OUT + c0]) =
                    make_float2(acc[mt][nt][0], acc[mt][nt][1]);
            if (r1 < N_NODES)
                *reinterpret_cast<float2*>(&g_seq[(size_t)r1 * D_OUT + c0]) =
                    make_float2(acc[mt][nt][2], acc[mt][nt][3]);
        }
    }
}

// ---------------------------------------------------------------------------
// init: out[n][c] = bias[c]  (vectorized float4; bias has 128 floats = 32 f4)
// ---------------------------------------------------------------------------
__global__ __launch_bounds__(256) void gcn_init_kernel(
    float4* __restrict__ out4, const float4* __restrict__ bias4)
{
    int i = blockIdx.x * blockDim.x + threadIdx.x;
    if (i < N_NODES * (D_OUT / 4)) {
        out4[i] = bias4[i & 31];
    }
}

// ---------------------------------------------------------------------------
// scatter: one warp per edge.
// out[row] += val * seq[col]   via red.global.add.v4.f32 (1 RED.128 per lane)
// ---------------------------------------------------------------------------
__global__ __launch_bounds__(256) void gcn_scatter_kernel(
    const float* __restrict__ edge_val,
    const int*   __restrict__ edge_row,
    const int*   __restrict__ edge_col,
    float*       __restrict__ out)
{
    int e = (int)((blockIdx.x * blockDim.x + threadIdx.x) >> 5);
    if (e >= N_EDGES) return;
    int lane = threadIdx.x & 31;

    int   row = __ldg(edge_row + e);
    int   col = __ldg(edge_col + e);
    float v   = __ldg(edge_val + e);

    const float4 s = *(reinterpret_cast<const float4*>(g_seq) +
                       (size_t)col * (D_OUT / 4) + lane);
    float4* dst = reinterpret_cast<float4*>(out) + (size_t)row * (D_OUT / 4) + lane;

    asm volatile(
        "red.global.add.v4.f32 [%0], {%1, %2, %3, %4};"
        :: "l"(dst), "f"(s.x * v), "f"(s.y * v), "f"(s.z * v), "f"(s.w * v)
        : "memory");
}

// ---------------------------------------------------------------------------
// PReLU epilogue: out = out > 0 ? out : alpha * out   (single shared alpha)
// ---------------------------------------------------------------------------
__global__ __launch_bounds__(256) void gcn_prelu_kernel(
    float4* __restrict__ out4, const float* __restrict__ alpha)
{
    int i = blockIdx.x * blockDim.x + threadIdx.x;
    if (i < N_NODES * (D_OUT / 4)) {
        float a  = __ldg(alpha);
        float4 v = out4[i];
        v.x = v.x > 0.f ? v.x : a * v.x;
        v.y = v.y > 0.f ? v.y : a * v.y;
        v.z = v.z > 0.f ? v.z : a * v.z;
        v.w = v.w > 0.f ? v.w : a * v.w;
        out4[i] = v;
    }
}

// ---------------------------------------------------------------------------
// Inputs (metadata order): x, weight, bias, alpha, edge_val, edge_row, edge_col
// Output: float32 [40000, 128]
// ---------------------------------------------------------------------------
extern "C" void kernel_launch(void* const* d_in, const int* in_sizes, int n_in,
                              void* d_out, int out_size)
{
    const float* x        = (const float*)d_in[0];
    const float* weight   = (const float*)d_in[1];
    const float* bias     = (const float*)d_in[2];
    const float* alpha    = (const float*)d_in[3];
    const float* edge_val = (const float*)d_in[4];
    const int*   edge_row = (const int*)  d_in[5];
    const int*   edge_col = (const int*)  d_in[6];
    float*       out      = (float*)d_out;

    (void)in_sizes; (void)n_in; (void)out_size;

    // 1) seq = x @ W^T  (tensor cores, tf32)
    gcn_gemm_tf32_kernel<<<(N_NODES + 127) / 128, 256>>>(x, weight);

    // 2) out = bias (broadcast)
    const int n4 = N_NODES * (D_OUT / 4);
    gcn_init_kernel<<<(n4 + 255) / 256, 256>>>(
        (float4*)out, (const float4*)bias);

    // 3) out[row] += val * seq[col] for every edge (vector RED atomics)
    const long long threads = (long long)N_EDGES * 32;
    gcn_scatter_kernel<<<(unsigned)((threads + 255) / 256), 256>>>(
        edge_val, edge_row, edge_col, out);

    // 4) PReLU
    gcn_prelu_kernel<<<(n4 + 255) / 256, 256>>>((float4*)out, alpha);
}